// round 2
// baseline (speedup 1.0000x reference)
#include <cuda_runtime.h>
#include <cstdint>

// Problem constants
#define Bn    32
#define Tn    2048
#define XD    64
#define ZD    128
#define Hh    512
#define TAU   16
#define DSUM  (XD + ZD)   // 192

#define OUT_ELEMS   ((size_t)Bn * Tn * XD)            // 4,194,304
// influence follows output in d_out
// influence elems = 16*64*192*512 = 100,663,296

// ---------------- scratch (device globals; no allocation allowed) ----------------
__device__ float g_v[(size_t)XD * TAU * DSUM];        // v[i][k][d]   (64*16*192)
__device__ float g_vx_t[TAU * XD * XD];               // vx_t[k][d][i] (16*64*64)
__device__ float g_vzp_t[ZD * XD];                    // vzp_t[d][i]  sum_k vz  (128*64)
__device__ float g_vz_pre[XD * (TAU + 1) * ZD];       // vz_pre[i][m][d]
__device__ float g_c_pre[XD * (TAU + 1)];             // c_pre[i][m]
__device__ float g_csum[XD];                          // c_pre[i][16]

// ---------------- cp.async helpers ----------------
__device__ __forceinline__ void cp_async16(float* smem_dst, const float* gmem_src) {
    uint32_t s = (uint32_t)__cvta_generic_to_shared(smem_dst);
    asm volatile("cp.async.ca.shared.global [%0], [%1], 16;\n" :: "r"(s), "l"(gmem_src));
}
__device__ __forceinline__ void cp_commit() { asm volatile("cp.async.commit_group;\n"); }
__device__ __forceinline__ void cp_wait0()  { asm volatile("cp.async.wait_group 0;\n"); }

// =====================================================================
// K1: stream W1 once -> write transposed influence AND reduce v = W1 @ W2
// grid 1024 (= i*16+k), 256 threads (8 warps, warp owns d = warp, warp+8, ...)
// =====================================================================
__global__ __launch_bounds__(256) void k_transpose_v(
    const float* __restrict__ W1, const float* __restrict__ W2,
    float* __restrict__ inf)
{
    int ik = blockIdx.x;
    int i = ik >> 4, k = ik & 15;
    int tid = threadIdx.x, warp = tid >> 5, lane = tid & 31;

    const float* w1b = W1 + (size_t)ik * (DSUM * Hh);
    const float* w2b = W2 + (size_t)ik * Hh;
    float* infb = inf + (size_t)(k * XD + i) * (DSUM * Hh);

    float4 w2r[4];
#pragma unroll
    for (int q = 0; q < 4; ++q)
        w2r[q] = reinterpret_cast<const float4*>(w2b)[lane + 32 * q];

    for (int d = warp; d < DSUM; d += 8) {
        const float4* row = reinterpret_cast<const float4*>(w1b + (size_t)d * Hh);
        float4* orow      = reinterpret_cast<float4*>(infb + (size_t)d * Hh);
        float s = 0.f;
#pragma unroll
        for (int q = 0; q < 4; ++q) {
            float4 a = row[lane + 32 * q];
            orow[lane + 32 * q] = a;
            s += a.x * w2r[q].x + a.y * w2r[q].y + a.z * w2r[q].z + a.w * w2r[q].w;
        }
#pragma unroll
        for (int o = 16; o; o >>= 1) s += __shfl_down_sync(0xffffffffu, s, o);
        if (lane == 0) g_v[(size_t)ik * DSUM + d] = s;
    }
}

// =====================================================================
// K2: per-i prep: c[i][k], prefix sums, vz prefix sums, weight transposes.
// grid 64 (= i), 128 threads
// =====================================================================
__global__ __launch_bounds__(128) void k_prep(
    const float* __restrict__ b1, const float* __restrict__ W2,
    const float* __restrict__ b2)
{
    int i = blockIdx.x;
    int tid = threadIdx.x, warp = tid >> 5, lane = tid & 31;
    __shared__ float c_s[TAU];

    for (int k = warp; k < TAU; k += 4) {
        const float4* b1r = reinterpret_cast<const float4*>(b1 + (size_t)(i * TAU + k) * Hh);
        const float4* w2r = reinterpret_cast<const float4*>(W2 + (size_t)(i * TAU + k) * Hh);
        float s = 0.f;
#pragma unroll
        for (int q = 0; q < 4; ++q) {
            float4 a = b1r[lane + 32 * q];
            float4 w = w2r[lane + 32 * q];
            s += a.x * w.x + a.y * w.y + a.z * w.z + a.w * w.w;
        }
#pragma unroll
        for (int o = 16; o; o >>= 1) s += __shfl_down_sync(0xffffffffu, s, o);
        if (lane == 0) c_s[k] = s + b2[i * TAU + k];
    }
    __syncthreads();

    if (tid == 0) {
        float run = 0.f;
        for (int m = 0; m <= TAU; ++m) {
            g_c_pre[i * (TAU + 1) + m] = run;
            if (m < TAU) run += c_s[m];
        }
        g_csum[i] = run;
    }
    if (tid < ZD) {
        int d = tid;
        float run = 0.f;
        for (int m = 0; m <= TAU; ++m) {
            g_vz_pre[(size_t)(i * (TAU + 1) + m) * ZD + d] = run;
            if (m < TAU) run += g_v[((size_t)(i * TAU + m)) * DSUM + XD + d];
        }
        g_vzp_t[d * XD + i] = run;
    }
    for (int idx = tid; idx < TAU * XD; idx += 128) {
        int k = idx >> 6, d = idx & 63;
        g_vx_t[(k * XD + d) * XD + i] = g_v[((size_t)(i * TAU + k)) * DSUM + d];
    }
}

// =====================================================================
// K3: main output kernel. Block tile = 64 t x 64 i, 128 threads,
// thread tile = 4 t x 8 i (32 accumulators). Double-buffered vx slices
// via cp.async. Uses full-k prefix weights (valid for t>=16); first-16-t
// outputs are recomputed exactly by k_fixup afterwards.
// Smem floats: x 80x66 + z 64x130 + w 2x4096 = 21792 (87168 B)
// =====================================================================
#define XS_STRIDE 66
#define ZS_STRIDE 130
#define XS_F (80 * XS_STRIDE)       // 5280
#define ZS_F (64 * ZS_STRIDE)       // 8320
#define WS_OFF (XS_F + ZS_F)        // 13600
#define SMEM_F (WS_OFF + 2 * 4096)  // 21792
#define SMEM_BYTES (SMEM_F * 4)     // 87168

__global__ __launch_bounds__(128) void k_main(
    const float* __restrict__ z, const float* __restrict__ x,
    float* __restrict__ out)
{
    extern __shared__ float sm[];
    float* x_s = sm;
    float* z_s = sm + XS_F;
    float* w_s = sm + WS_OFF;

    int tid = threadIdx.x;
    int tx = tid & 7;          // i-octet
    int ty = tid >> 3;         // t-quad (0..15)
    int b  = blockIdx.y;
    int t0 = blockIdx.x * 64;

    // ---- fill x tile (rows t0-16 .. t0+63), zero-pad t<0 ----
    const float* xb = x + ((size_t)b * Tn) * XD;
    for (int idx = tid; idx < 80 * XD; idx += 128) {
        int s = idx >> 6, d = idx & 63;
        int t = t0 - TAU + s;
        x_s[s * XS_STRIDE + d] = (t >= 0) ? xb[(size_t)t * XD + d] : 0.f;
    }
    // ---- fill z tile ----
    const float* zb = z + ((size_t)b * Tn + t0) * ZD;
    for (int idx = tid; idx < 64 * ZD; idx += 128) {
        int tt = idx >> 7, d = idx & 127;
        z_s[tt * ZS_STRIDE + d] = zb[(size_t)tt * ZD + d];
    }
    // ---- preload first vx slice (k=0): 4096 floats ----
#pragma unroll
    for (int q = 0; q < 8; ++q) {
        int f4i = q * 128 + tid;
        cp_async16(w_s + f4i * 4, g_vx_t + f4i * 4);
    }
    cp_commit();
    cp_wait0();
    __syncthreads();

    float acc[4][8];
#pragma unroll
    for (int j = 0; j < 4; ++j)
#pragma unroll
        for (int m = 0; m < 8; ++m) acc[j][m] = 0.f;

    int cur = 0;
    int ty4 = ty * 4;

    // ---- causal conv: 16 taps ----
    for (int k = 0; k < TAU; ++k) {
        if (k < TAU - 1) {
            float* dst = w_s + (cur ^ 1) * 4096;
            const float* src = g_vx_t + (k + 1) * 4096;
#pragma unroll
            for (int q = 0; q < 8; ++q) {
                int f4i = q * 128 + tid;
                cp_async16(dst + f4i * 4, src + f4i * 4);
            }
            cp_commit();
        }
        const float* wb = w_s + cur * 4096;
        const float* xk = x_s + (TAU - 1 - k + ty4) * XS_STRIDE;
#pragma unroll 4
        for (int d = 0; d < XD; ++d) {
            float4 w0 = *reinterpret_cast<const float4*>(wb + (d << 6) + (tx << 3));
            float4 w1 = *reinterpret_cast<const float4*>(wb + (d << 6) + (tx << 3) + 4);
#pragma unroll
            for (int j = 0; j < 4; ++j) {
                float xv = xk[j * XS_STRIDE + d];
                acc[j][0] = fmaf(xv, w0.x, acc[j][0]);
                acc[j][1] = fmaf(xv, w0.y, acc[j][1]);
                acc[j][2] = fmaf(xv, w0.z, acc[j][2]);
                acc[j][3] = fmaf(xv, w0.w, acc[j][3]);
                acc[j][4] = fmaf(xv, w1.x, acc[j][4]);
                acc[j][5] = fmaf(xv, w1.y, acc[j][5]);
                acc[j][6] = fmaf(xv, w1.z, acc[j][6]);
                acc[j][7] = fmaf(xv, w1.w, acc[j][7]);
            }
        }
        cp_wait0();
        __syncthreads();
        cur ^= 1;
    }

    // ---- z part: load vzp_t (128x64 = 8192 floats) into w area ----
#pragma unroll
    for (int q = 0; q < 16; ++q) {
        int f4i = q * 128 + tid;
        cp_async16(w_s + f4i * 4, g_vzp_t + f4i * 4);
    }
    cp_commit();
    cp_wait0();
    __syncthreads();

#pragma unroll 4
    for (int d = 0; d < ZD; ++d) {
        float4 w0 = *reinterpret_cast<const float4*>(w_s + (d << 6) + (tx << 3));
        float4 w1 = *reinterpret_cast<const float4*>(w_s + (d << 6) + (tx << 3) + 4);
#pragma unroll
        for (int j = 0; j < 4; ++j) {
            float zv = z_s[(ty4 + j) * ZS_STRIDE + d];
            acc[j][0] = fmaf(zv, w0.x, acc[j][0]);
            acc[j][1] = fmaf(zv, w0.y, acc[j][1]);
            acc[j][2] = fmaf(zv, w0.z, acc[j][2]);
            acc[j][3] = fmaf(zv, w0.w, acc[j][3]);
            acc[j][4] = fmaf(zv, w1.x, acc[j][4]);
            acc[j][5] = fmaf(zv, w1.y, acc[j][5]);
            acc[j][6] = fmaf(zv, w1.z, acc[j][6]);
            acc[j][7] = fmaf(zv, w1.w, acc[j][7]);
        }
    }

    // ---- epilogue: + c_sum, store ----
    int ibase = tx * 8;
    float cs[8];
#pragma unroll
    for (int m = 0; m < 8; ++m) cs[m] = g_csum[ibase + m];
#pragma unroll
    for (int j = 0; j < 4; ++j) {
        float* o = out + ((size_t)(b * Tn + t0 + ty4 + j)) * XD + ibase;
        float4 o0, o1;
        o0.x = acc[j][0] + cs[0]; o0.y = acc[j][1] + cs[1];
        o0.z = acc[j][2] + cs[2]; o0.w = acc[j][3] + cs[3];
        o1.x = acc[j][4] + cs[4]; o1.y = acc[j][5] + cs[5];
        o1.z = acc[j][6] + cs[6]; o1.w = acc[j][7] + cs[7];
        reinterpret_cast<float4*>(o)[0] = o0;
        reinterpret_cast<float4*>(o)[1] = o1;
    }
}

// =====================================================================
// K4: exact recompute of the first 16 timesteps per batch (partial k sums).
// grid (16 t, 32 b), 64 threads (= i). Tiny.
// =====================================================================
__global__ __launch_bounds__(64) void k_fixup(
    const float* __restrict__ z, const float* __restrict__ x,
    float* __restrict__ out)
{
    int i = threadIdx.x;
    int t = blockIdx.x;     // 0..15
    int b = blockIdx.y;

    float acc = g_c_pre[i * (TAU + 1) + t];
    const float* zr  = z + ((size_t)b * Tn + t) * ZD;
    const float* vzp = g_vz_pre + (size_t)(i * (TAU + 1) + t) * ZD;
#pragma unroll 4
    for (int d = 0; d < ZD; ++d) acc = fmaf(zr[d], vzp[d], acc);

    for (int k = 0; k < t; ++k) {
        const float* xr  = x + ((size_t)b * Tn + (t - 1 - k)) * XD;
        const float* vxr = g_v + ((size_t)(i * TAU + k)) * DSUM;
#pragma unroll 4
        for (int d = 0; d < XD; ++d) acc = fmaf(xr[d], vxr[d], acc);
    }
    out[((size_t)b * Tn + t) * XD + i] = acc;
}

// =====================================================================
extern "C" void kernel_launch(void* const* d_in, const int* in_sizes, int n_in,
                              void* d_out, int out_size)
{
    const float* z   = (const float*)d_in[0];
    const float* x   = (const float*)d_in[1];
    const float* W1  = (const float*)d_in[2];
    const float* b1  = (const float*)d_in[3];
    const float* W2  = (const float*)d_in[4];
    const float* b2  = (const float*)d_in[5];

    float* out = (float*)d_out;
    float* inf = out + OUT_ELEMS;

    cudaFuncSetAttribute(k_main, cudaFuncAttributeMaxDynamicSharedMemorySize, SMEM_BYTES);

    k_transpose_v<<<XD * TAU, 256>>>(W1, W2, inf);
    k_prep<<<XD, 128>>>(b1, W2, b2);
    k_main<<<dim3(Tn / 64, Bn), 128, SMEM_BYTES>>>(z, x, out);
    k_fixup<<<dim3(TAU, Bn), 64>>>(z, x, out);
}

// round 3
// speedup vs baseline: 1.4983x; 1.4983x over previous
#include <cuda_runtime.h>
#include <cstdint>

typedef unsigned long long ull;

// Problem constants
#define Bn    32
#define Tn    2048
#define XD    64
#define ZD    128
#define Hh    512
#define TAU   16
#define DSUM  (XD + ZD)   // 192

#define OUT_ELEMS   ((size_t)Bn * Tn * XD)            // 4,194,304

// ---------------- scratch (device globals; no allocation allowed) ----------------
__device__ float g_v[(size_t)XD * TAU * DSUM];           // v[i][k][d]
__device__ float g_vx_t[TAU * XD * XD];                  // [k][d][i]
__device__ float g_vzp_t[ZD * XD];                       // [d][i]  (full-k vz sum)
__device__ float g_vz_pre_t[(TAU + 1) * ZD * XD];        // [m][d][i]
__device__ float g_c_pre_t[(TAU + 1) * XD];              // [m][i]
__device__ float g_csum[XD];

// ---------------- helpers ----------------
__device__ __forceinline__ void cp_async16(void* smem_dst, const void* gmem_src) {
    uint32_t s = (uint32_t)__cvta_generic_to_shared(smem_dst);
    asm volatile("cp.async.ca.shared.global [%0], [%1], 16;\n" :: "r"(s), "l"(gmem_src));
}
__device__ __forceinline__ void cp_async4(void* smem_dst, const void* gmem_src) {
    uint32_t s = (uint32_t)__cvta_generic_to_shared(smem_dst);
    asm volatile("cp.async.ca.shared.global [%0], [%1], 4;\n" :: "r"(s), "l"(gmem_src));
}
__device__ __forceinline__ void cp_commit() { asm volatile("cp.async.commit_group;\n"); }
__device__ __forceinline__ void cp_wait0()  { asm volatile("cp.async.wait_group 0;\n"); }

__device__ __forceinline__ ull pack2(float lo, float hi) {
    ull r; asm("mov.b64 %0, {%1,%2};" : "=l"(r) : "f"(lo), "f"(hi)); return r;
}
__device__ __forceinline__ void fma2(ull& d, ull a, ull b) {
    asm("fma.rn.f32x2 %0, %1, %2, %0;" : "+l"(d) : "l"(a), "l"(b));
}
__device__ __forceinline__ ull add2(ull a, ull b) {
    ull r; asm("add.rn.f32x2 %0, %1, %2;" : "=l"(r) : "l"(a), "l"(b)); return r;
}

// =====================================================================
// K1: stream W1 once -> transposed influence + v = W1 @ W2 (HBM-bound)
// =====================================================================
__global__ __launch_bounds__(256) void k_transpose_v(
    const float* __restrict__ W1, const float* __restrict__ W2,
    float* __restrict__ inf)
{
    int ik = blockIdx.x;
    int i = ik >> 4, k = ik & 15;
    int tid = threadIdx.x, warp = tid >> 5, lane = tid & 31;

    const float* w1b = W1 + (size_t)ik * (DSUM * Hh);
    const float* w2b = W2 + (size_t)ik * Hh;
    float* infb = inf + (size_t)(k * XD + i) * (DSUM * Hh);

    float4 w2r[4];
#pragma unroll
    for (int q = 0; q < 4; ++q)
        w2r[q] = reinterpret_cast<const float4*>(w2b)[lane + 32 * q];

    for (int d = warp; d < DSUM; d += 8) {
        const float4* row = reinterpret_cast<const float4*>(w1b + (size_t)d * Hh);
        float4* orow      = reinterpret_cast<float4*>(infb + (size_t)d * Hh);
        float s = 0.f;
#pragma unroll
        for (int q = 0; q < 4; ++q) {
            float4 a = row[lane + 32 * q];
            orow[lane + 32 * q] = a;
            s += a.x * w2r[q].x + a.y * w2r[q].y + a.z * w2r[q].z + a.w * w2r[q].w;
        }
#pragma unroll
        for (int o = 16; o; o >>= 1) s += __shfl_down_sync(0xffffffffu, s, o);
        if (lane == 0) g_v[(size_t)ik * DSUM + d] = s;
    }
}

// =====================================================================
// K2: per-i prep: c prefix, vz prefix (transposed layouts), vx transpose
// =====================================================================
__global__ __launch_bounds__(128) void k_prep(
    const float* __restrict__ b1, const float* __restrict__ W2,
    const float* __restrict__ b2)
{
    int i = blockIdx.x;
    int tid = threadIdx.x, warp = tid >> 5, lane = tid & 31;
    __shared__ float c_s[TAU];

    for (int k = warp; k < TAU; k += 4) {
        const float4* b1r = reinterpret_cast<const float4*>(b1 + (size_t)(i * TAU + k) * Hh);
        const float4* w2r = reinterpret_cast<const float4*>(W2 + (size_t)(i * TAU + k) * Hh);
        float s = 0.f;
#pragma unroll
        for (int q = 0; q < 4; ++q) {
            float4 a = b1r[lane + 32 * q];
            float4 w = w2r[lane + 32 * q];
            s += a.x * w.x + a.y * w.y + a.z * w.z + a.w * w.w;
        }
#pragma unroll
        for (int o = 16; o; o >>= 1) s += __shfl_down_sync(0xffffffffu, s, o);
        if (lane == 0) c_s[k] = s + b2[i * TAU + k];
    }
    __syncthreads();

    if (tid == 0) {
        float run = 0.f;
        for (int m = 0; m <= TAU; ++m) {
            g_c_pre_t[m * XD + i] = run;
            if (m < TAU) run += c_s[m];
        }
        g_csum[i] = run;
    }
    if (tid < ZD) {
        int d = tid;
        float run = 0.f;
        for (int m = 0; m <= TAU; ++m) {
            g_vz_pre_t[(size_t)(m * ZD + d) * XD + i] = run;
            if (m < TAU) run += g_v[((size_t)(i * TAU + m)) * DSUM + XD + d];
        }
        g_vzp_t[d * XD + i] = run;
    }
    for (int idx = tid; idx < TAU * XD; idx += 128) {
        int k = idx >> 6, d = idx & 63;
        g_vx_t[(k * XD + d) * XD + i] = g_v[((size_t)(i * TAU + k)) * DSUM + d];
    }
}

// =====================================================================
// K3: main kernel. Block tile 128t x 64i, 128 threads, thread tile
// 8t x 8i, accumulators as 32 packed f32x2. Double-buffered weight
// slices via cp.async; z processed in 2 d-chunks of 64.
// Smem floats: x 144x65 + z 128x65 + w 2x4096 = 25872 (103,488 B)
// =====================================================================
#define XSS 65
#define ZSS 65
#define XS_F (144 * XSS)            // 9360
#define ZS_F (128 * ZSS)            // 8320
#define WS_OFF (XS_F + ZS_F)        // 17680
#define SMEM_F (WS_OFF + 2 * 4096)  // 25872
#define SMEM_BYTES (SMEM_F * 4)     // 103488

__global__ void __launch_bounds__(128, 2) k_main(
    const float* __restrict__ z, const float* __restrict__ x,
    float* __restrict__ out)
{
    extern __shared__ float sm[];
    float* x_s = sm;
    float* z_s = sm + XS_F;
    float* w_s = sm + WS_OFF;

    int tid = threadIdx.x;
    int tx = tid & 7;          // i-octet
    int ty = tid >> 3;         // 0..15
    int ty8 = ty * 8;
    int b  = blockIdx.y;
    int t0 = blockIdx.x * 128;

    // ---- fill x tile rows t0-16 .. t0+127 (zero-pad t<0) ----
    const float* xb = x + (size_t)b * Tn * XD;
    for (int idx = tid; idx < 144 * 16; idx += 128) {
        int s = idx >> 4, q = idx & 15;
        int t = t0 - TAU + s;
        float4 v = (t >= 0) ? reinterpret_cast<const float4*>(xb + (size_t)t * XD)[q]
                            : make_float4(0.f, 0.f, 0.f, 0.f);
        float* r = x_s + s * XSS + q * 4;
        r[0] = v.x; r[1] = v.y; r[2] = v.z; r[3] = v.w;
    }
    // ---- preload conv tap 0 ----
#pragma unroll
    for (int q = 0; q < 8; ++q) {
        int f = q * 128 + tid;
        cp_async16(w_s + f * 4, g_vx_t + f * 4);
    }
    cp_commit();
    cp_wait0();
    __syncthreads();

    ull acc[8][4];
#pragma unroll
    for (int j = 0; j < 8; ++j)
#pragma unroll
        for (int p = 0; p < 4; ++p) acc[j][p] = 0ull;

    int cur = 0;
    const float* zb = z + ((size_t)b * Tn + t0) * ZD;

    // ---- causal conv: 16 taps ----
    for (int k = 0; k < TAU; ++k) {
        if (k < TAU - 1) {
            float* dst = w_s + ((cur ^ 1) << 12);
            const float* src = g_vx_t + (k + 1) * 4096;
#pragma unroll
            for (int q = 0; q < 8; ++q) {
                int f = q * 128 + tid;
                cp_async16(dst + f * 4, src + f * 4);
            }
            cp_commit();
        } else {
            // final tap: prefetch vzp chunk 0 + z chunk 0
            float* dst = w_s + ((cur ^ 1) << 12);
#pragma unroll
            for (int q = 0; q < 8; ++q) {
                int f = q * 128 + tid;
                cp_async16(dst + f * 4, g_vzp_t + f * 4);
            }
#pragma unroll 8
            for (int n = 0; n < 64; ++n) {
                int idx = n * 128 + tid;
                int r = idx >> 6, c2 = idx & 63;
                cp_async4(z_s + r * ZSS + c2, zb + (size_t)r * ZD + c2);
            }
            cp_commit();
        }

        const float* wb = w_s + (cur << 12);
        const float* xk = x_s + (TAU - 1 - k + ty8) * XSS;
#pragma unroll 4
        for (int d = 0; d < XD; ++d) {
            const ulonglong2* wp = reinterpret_cast<const ulonglong2*>(wb + (d << 6) + (tx << 3));
            ulonglong2 wa = wp[0];
            ulonglong2 wc = wp[1];
#pragma unroll
            for (int j = 0; j < 8; ++j) {
                float xv = xk[j * XSS + d];
                ull xx = pack2(xv, xv);
                fma2(acc[j][0], xx, wa.x);
                fma2(acc[j][1], xx, wa.y);
                fma2(acc[j][2], xx, wc.x);
                fma2(acc[j][3], xx, wc.y);
            }
        }
        cp_wait0();
        __syncthreads();
        cur ^= 1;
    }

    // ---- z GEMM, two d-chunks of 64 ----
    // chunk 0 weights+data are ready in w_s[cur] / z_s. Prefetch vzp chunk 1.
    {
        float* dst = w_s + ((cur ^ 1) << 12);
#pragma unroll
        for (int q = 0; q < 8; ++q) {
            int f = q * 128 + tid;
            cp_async16(dst + f * 4, g_vzp_t + 4096 + f * 4);
        }
        cp_commit();
    }
#pragma unroll
    for (int c = 0; c < 2; ++c) {
        const float* wb = w_s + (cur << 12);
        const float* zk = z_s + ty8 * ZSS;
#pragma unroll 4
        for (int d = 0; d < 64; ++d) {
            const ulonglong2* wp = reinterpret_cast<const ulonglong2*>(wb + (d << 6) + (tx << 3));
            ulonglong2 wa = wp[0];
            ulonglong2 wc = wp[1];
#pragma unroll
            for (int j = 0; j < 8; ++j) {
                float zv = zk[j * ZSS + d];
                ull zz = pack2(zv, zv);
                fma2(acc[j][0], zz, wa.x);
                fma2(acc[j][1], zz, wa.y);
                fma2(acc[j][2], zz, wc.x);
                fma2(acc[j][3], zz, wc.y);
            }
        }
        if (c == 0) {
            __syncthreads();          // everyone done reading z_s chunk 0
#pragma unroll 8
            for (int n = 0; n < 64; ++n) {
                int idx = n * 128 + tid;
                int r = idx >> 6, c2 = idx & 63;
                cp_async4(z_s + r * ZSS + c2, zb + (size_t)r * ZD + 64 + c2);
            }
            cp_commit();
            cp_wait0();
            __syncthreads();
            cur ^= 1;
        }
    }

    // ---- epilogue: + csum, store ----
    const ull* cp = reinterpret_cast<const ull*>(g_csum) + tx * 4;
    ull cs0 = cp[0], cs1 = cp[1], cs2 = cp[2], cs3 = cp[3];
#pragma unroll
    for (int j = 0; j < 8; ++j) {
        ulonglong2 o0, o1;
        o0.x = add2(acc[j][0], cs0);
        o0.y = add2(acc[j][1], cs1);
        o1.x = add2(acc[j][2], cs2);
        o1.y = add2(acc[j][3], cs3);
        float* o = out + ((size_t)(b * Tn + t0 + ty8 + j)) * XD + tx * 8;
        reinterpret_cast<ulonglong2*>(o)[0] = o0;
        reinterpret_cast<ulonglong2*>(o)[1] = o1;
    }
}

// =====================================================================
// K4: exact recompute of first 16 timesteps — coalesced weight loads.
// grid (16 t, 32 b), 64 threads (= i).
// =====================================================================
__global__ __launch_bounds__(64) void k_fixup(
    const float* __restrict__ z, const float* __restrict__ x,
    float* __restrict__ out)
{
    int i = threadIdx.x;
    int t = blockIdx.x;     // 0..15
    int b = blockIdx.y;

    __shared__ float zr[ZD];
    __shared__ float xr[15 * 64];

    zr[i]      = z[((size_t)b * Tn + t) * ZD + i];
    zr[i + 64] = z[((size_t)b * Tn + t) * ZD + 64 + i];
    for (int idx = i; idx < t * 64; idx += 64) {
        int k = idx >> 6, d = idx & 63;
        xr[idx] = x[((size_t)b * Tn + (t - 1 - k)) * XD + d];
    }
    __syncthreads();

    float acc = g_c_pre_t[t * XD + i];
    const float* vz = g_vz_pre_t + (size_t)t * ZD * XD + i;
#pragma unroll 8
    for (int d = 0; d < ZD; ++d)
        acc = fmaf(zr[d], vz[(size_t)d * XD], acc);

    for (int k = 0; k < t; ++k) {
        const float* vx = g_vx_t + k * 4096 + i;
#pragma unroll 8
        for (int d = 0; d < XD; ++d)
            acc = fmaf(xr[k * 64 + d], vx[d * XD], acc);
    }
    out[((size_t)b * Tn + t) * XD + i] = acc;
}

// =====================================================================
extern "C" void kernel_launch(void* const* d_in, const int* in_sizes, int n_in,
                              void* d_out, int out_size)
{
    const float* z   = (const float*)d_in[0];
    const float* x   = (const float*)d_in[1];
    const float* W1  = (const float*)d_in[2];
    const float* b1  = (const float*)d_in[3];
    const float* W2  = (const float*)d_in[4];
    const float* b2  = (const float*)d_in[5];

    float* out = (float*)d_out;
    float* inf = out + OUT_ELEMS;

    cudaFuncSetAttribute(k_main, cudaFuncAttributeMaxDynamicSharedMemorySize, SMEM_BYTES);

    k_transpose_v<<<XD * TAU, 256>>>(W1, W2, inf);
    k_prep<<<XD, 128>>>(b1, W2, b2);
    k_main<<<dim3(Tn / 128, Bn), 128, SMEM_BYTES>>>(z, x, out);
    k_fixup<<<dim3(TAU, Bn), 64>>>(z, x, out);
}